// round 7
// baseline (speedup 1.0000x reference)
#include <cuda_runtime.h>
#include <cuda_fp16.h>
#include <math.h>

#define BB 8
#define SS 512
#define HH 256
#define AA 64
#define ROWS (BB*SS)   // 4096
#define TI 8           // i-rows per attn block

// Scratch (allocation-free rule: __device__ globals)
__device__ float        g_ta[ROWS * AA];         // [row][a], bias folded in (f32)
__device__ unsigned int g_jaT16[(AA/2) * ROWS];  // [a-pair][row], half2 (ja_2p, ja_2p+1)

namespace rk {

// packed f32x2 helpers (Blackwell FFMA2 — only reachable via PTX fma.rn.f32x2)
union F2 { unsigned long long u; float2 f; };

__device__ __forceinline__ unsigned long long fma2(
    unsigned long long a, unsigned long long b, unsigned long long c) {
    unsigned long long d;
    asm("fma.rn.f32x2 %0, %1, %2, %3;" : "=l"(d) : "l"(a), "l"(b), "l"(c));
    return d;
}

// fast packed tanh (MUFU.TANH f16x2) — unique name, no header collision
__device__ __forceinline__ __half2 rk_tanh_f16x2(__half2 x) {
    unsigned int xi = *reinterpret_cast<unsigned int*>(&x);
    unsigned int yi;
    asm("tanh.approx.f16x2 %0, %1;" : "=r"(yi) : "r"(xi));
    return *reinterpret_cast<__half2*>(&yi);
}

} // namespace rk

using rk::F2;
using rk::fma2;
using rk::rk_tanh_f16x2;

// ---------------------------------------------------------------------------
// Kernel 1: tiled GEMM with packed f32x2 FMA. 128 blocks x 256 threads.
// Block: 32 rows x 128 cols. Thread (rt,ct): 4x4 micro-tile, cols paired.
// W is read DIRECTLY from w_ta/w_ja (k-contiguous float4 per a-row) and
// scattered into Ws[kk][a2] with conflict-free scalar STS (lanes vary a2).
// Epilogue: ta -> f32 [row][a] (+bias); ja -> f16x2 [a-pair][row].
// ---------------------------------------------------------------------------
#define KC 64
__global__ void __launch_bounds__(256) proj_gemm_kernel(
    const float* __restrict__ x,
    const float* __restrict__ w_ta,
    const float* __restrict__ w_ja,
    const float* __restrict__ bias)
{
    __shared__ float Xs[32][KC];        // [r][kk]  8KB
    __shared__ float Ws[KC][128];       // [kk][a2] 32KB

    const int tid = threadIdx.x;
    const int rt  = tid >> 5;           // 0..7  (row tile)
    const int ct  = tid & 31;           // 0..31 (col tile)
    const int row0 = blockIdx.x * 32;

    // W-load role (constant across tiles): this thread always loads a2w's row
    const int a2w = tid & 127;          // which output column's weights
    const int hiw = tid >> 7;           // 0 or 1
    const float* wsrc = (a2w < 64) ? (w_ta + (size_t)a2w * HH)
                                   : (w_ja + (size_t)(a2w - 64) * HH);

    F2 acc[4][2];                        // 4 rows x (2 col-pairs)
#pragma unroll
    for (int i = 0; i < 4; ++i) { acc[i][0].u = 0ull; acc[i][1].u = 0ull; }

    for (int kc = 0; kc < HH; kc += KC) {
        // X chunk: 32 rows x 64 k = 512 float4, 2 per thread (coalesced).
#pragma unroll
        for (int l = tid; l < 512; l += 256) {
            int r = l >> 4;
            int q = l & 15;
            float4 xv = *reinterpret_cast<const float4*>(
                x + (size_t)(row0 + r) * HH + kc + q * 4);
            *reinterpret_cast<float4*>(&Xs[r][q * 4]) = xv;
        }
        // W chunk: 64 kk x 128 a2. Thread reads float4 along k for its a2 row,
        // scatters 4 scalar STS (lanes have consecutive a2 -> conflict-free).
#pragma unroll
        for (int m = 0; m < 8; ++m) {
            int kk4 = 2 * m + hiw;      // 0..15
            float4 f = *reinterpret_cast<const float4*>(wsrc + kc + kk4 * 4);
            Ws[kk4 * 4 + 0][a2w] = f.x;
            Ws[kk4 * 4 + 1][a2w] = f.y;
            Ws[kk4 * 4 + 2][a2w] = f.z;
            Ws[kk4 * 4 + 3][a2w] = f.w;
        }
        __syncthreads();

#pragma unroll
        for (int kk = 0; kk < KC; ++kk) {
            ulonglong2 wv = *reinterpret_cast<ulonglong2*>(&Ws[kk][ct * 4]);
            F2 x0, x1, x2, x3;
            float a0 = Xs[rt * 4 + 0][kk];   // warp-broadcast LDS
            float a1 = Xs[rt * 4 + 1][kk];
            float a2v = Xs[rt * 4 + 2][kk];
            float a3 = Xs[rt * 4 + 3][kk];
            x0.f = make_float2(a0, a0);
            x1.f = make_float2(a1, a1);
            x2.f = make_float2(a2v, a2v);
            x3.f = make_float2(a3, a3);
            acc[0][0].u = fma2(x0.u, wv.x, acc[0][0].u);
            acc[0][1].u = fma2(x0.u, wv.y, acc[0][1].u);
            acc[1][0].u = fma2(x1.u, wv.x, acc[1][0].u);
            acc[1][1].u = fma2(x1.u, wv.y, acc[1][1].u);
            acc[2][0].u = fma2(x2.u, wv.x, acc[2][0].u);
            acc[2][1].u = fma2(x2.u, wv.y, acc[2][1].u);
            acc[3][0].u = fma2(x3.u, wv.x, acc[3][0].u);
            acc[3][1].u = fma2(x3.u, wv.y, acc[3][1].u);
        }
        __syncthreads();
    }

    const int c0 = ct * 4;
    if (c0 < 64) {
        // ta path: add bias, write [row][a] as float4 (f32)
        float4 bb = *reinterpret_cast<const float4*>(bias + c0);
#pragma unroll
        for (int i = 0; i < 4; ++i) {
            int row = row0 + rt * 4 + i;
            float4 o;
            o.x = acc[i][0].f.x + bb.x;
            o.y = acc[i][0].f.y + bb.y;
            o.z = acc[i][1].f.x + bb.z;
            o.w = acc[i][1].f.y + bb.w;
            *reinterpret_cast<float4*>(&g_ta[(size_t)row * AA + c0]) = o;
        }
    } else {
        // ja path: f16x2 over a-pairs, [a-pair][row]; 4 consecutive rows -> STG.128
        const int ab  = c0 - 64;        // multiple of 4
        const int ap0 = ab >> 1;        // a-pair indices ap0, ap0+1
        uint4 s0, s1;
        {
            __half2 h;
            h = __floats2half2_rn(acc[0][0].f.x, acc[0][0].f.y); s0.x = *reinterpret_cast<unsigned int*>(&h);
            h = __floats2half2_rn(acc[1][0].f.x, acc[1][0].f.y); s0.y = *reinterpret_cast<unsigned int*>(&h);
            h = __floats2half2_rn(acc[2][0].f.x, acc[2][0].f.y); s0.z = *reinterpret_cast<unsigned int*>(&h);
            h = __floats2half2_rn(acc[3][0].f.x, acc[3][0].f.y); s0.w = *reinterpret_cast<unsigned int*>(&h);
            h = __floats2half2_rn(acc[0][1].f.x, acc[0][1].f.y); s1.x = *reinterpret_cast<unsigned int*>(&h);
            h = __floats2half2_rn(acc[1][1].f.x, acc[1][1].f.y); s1.y = *reinterpret_cast<unsigned int*>(&h);
            h = __floats2half2_rn(acc[2][1].f.x, acc[2][1].f.y); s1.z = *reinterpret_cast<unsigned int*>(&h);
            h = __floats2half2_rn(acc[3][1].f.x, acc[3][1].f.y); s1.w = *reinterpret_cast<unsigned int*>(&h);
        }
        const int rowb = row0 + rt * 4;   // multiple of 4 -> 16B aligned
        *reinterpret_cast<uint4*>(&g_jaT16[(size_t)ap0 * ROWS + rowb])       = s0;
        *reinterpret_cast<uint4*>(&g_jaT16[(size_t)(ap0 + 1) * ROWS + rowb]) = s1;
    }
}

// ---------------------------------------------------------------------------
// Kernel 2: scores + softmax with f16x2 tanh + KAHAN f16x2 accumulation
// (no F2F on the xu pipe inside the loop). TI=8 i-rows per block.
// 512 blocks x 512 threads; thread = one j. i-pairs ride the f16x2 lanes.
// ---------------------------------------------------------------------------
__global__ void __launch_bounds__(512) attn_kernel(
    const float* __restrict__ v,
    float* __restrict__ out)
{
    __shared__ __half2 ta16[AA][4];     // [a][i-pair p], 16B rows -> LDS.128
    __shared__ __half2 v16[AA];         // dup(v_a)
    __shared__ float redm[TI][16];
    __shared__ float reds[TI][16];
    __shared__ float gmaxs[TI];
    __shared__ float sums[TI];

    const int blk = blockIdx.x;           // 0..511
    const int b   = blk >> 6;             // batch
    const int i0  = (blk & 63) * TI;      // first i-row
    const int j   = threadIdx.x;          // 0..511
    const int lane = j & 31;
    const int warp = j >> 5;              // 0..15

    // setup: pack ta into f16x2 i-pairs, dup v
    if (j < 256) {
        int a = j >> 2, p = j & 3;
        float lo = g_ta[(size_t)(b * SS + i0 + 2 * p)     * AA + a];
        float hi = g_ta[(size_t)(b * SS + i0 + 2 * p + 1) * AA + a];
        ta16[a][p] = __floats2half2_rn(lo, hi);
    } else if (j < 256 + AA) {
        int a = j - 256;
        v16[a] = __float2half2_rn(v[a]);
    }
    __syncthreads();

    // Kahan state per i-pair
    __half2 s2[4], c2[4];
#pragma unroll
    for (int p = 0; p < 4; ++p) {
        s2[p] = __float2half2_rn(0.f);
        c2[p] = __float2half2_rn(0.f);
    }

    const unsigned int* jp = g_jaT16 + b * SS + j;
#pragma unroll 4
    for (int ap = 0; ap < AA / 2; ++ap) {
        unsigned int jraw = jp[(size_t)ap * ROWS];
        __half2 jv  = *reinterpret_cast<__half2*>(&jraw);   // (ja_{2ap}, ja_{2ap+1})
        __half2 jv0 = __low2half2(jv);
        __half2 jv1 = __high2half2(jv);
        __half2 va0 = v16[2 * ap];
        __half2 va1 = v16[2 * ap + 1];
        // vectorized ta reads: one LDS.128 per a-row (broadcast)
        uint4 ra0 = *reinterpret_cast<const uint4*>(&ta16[2 * ap][0]);
        uint4 ra1 = *reinterpret_cast<const uint4*>(&ta16[2 * ap + 1][0]);
        const unsigned int* pa0 = reinterpret_cast<const unsigned int*>(&ra0);
        const unsigned int* pa1 = reinterpret_cast<const unsigned int*>(&ra1);
#pragma unroll
        for (int p = 0; p < 4; ++p) {
            __half2 t0 = rk_tanh_f16x2(__hadd2(*reinterpret_cast<const __half2*>(&pa0[p]), jv0));
            __half2 t1 = rk_tanh_f16x2(__hadd2(*reinterpret_cast<const __half2*>(&pa1[p]), jv1));
            __half2 u  = __hfma2(va1, t1, __hmul2(va0, t0));
            // Kahan (f16x2): carries ~20-bit effective precision, no F2F
            __half2 y  = __hsub2(u, c2[p]);
            __half2 t  = __hadd2(s2[p], y);
            c2[p] = __hsub2(__hsub2(t, s2[p]), y);
            s2[p] = t;
        }
    }

    // single conversion to f32 (xu cost: 16 F2F per thread, once)
    float acc[TI];
#pragma unroll
    for (int p = 0; p < 4; ++p) {
        float2 fs = __half22float2(s2[p]);
        float2 fc = __half22float2(c2[p]);
        acc[2 * p]     = fs.x + fc.x;
        acc[2 * p + 1] = fs.y + fc.y;
    }

    // ---- block max per row ----
#pragma unroll
    for (int i = 0; i < TI; ++i) {
        float mx = acc[i];
#pragma unroll
        for (int o = 16; o; o >>= 1) mx = fmaxf(mx, __shfl_xor_sync(0xffffffffu, mx, o));
        if (lane == 0) redm[i][warp] = mx;
    }
    __syncthreads();
    if (warp < TI) {
        float m = (lane < 16) ? redm[warp][lane] : -INFINITY;
#pragma unroll
        for (int o = 8; o; o >>= 1) m = fmaxf(m, __shfl_xor_sync(0xffffffffu, m, o));
        if (lane == 0) gmaxs[warp] = m;
    }
    __syncthreads();

    // ---- exp + block sum per row ----
    float e[TI];
#pragma unroll
    for (int i = 0; i < TI; ++i) {
        e[i] = __expf(acc[i] - gmaxs[i]);
        float sm = e[i];
#pragma unroll
        for (int o = 16; o; o >>= 1) sm += __shfl_xor_sync(0xffffffffu, sm, o);
        if (lane == 0) reds[i][warp] = sm;
    }
    __syncthreads();
    if (warp < TI) {
        float t = (lane < 16) ? reds[warp][lane] : 0.f;
#pragma unroll
        for (int o = 8; o; o >>= 1) t += __shfl_xor_sync(0xffffffffu, t, o);
        if (lane == 0) sums[warp] = t;
    }
    __syncthreads();

#pragma unroll
    for (int i = 0; i < TI; ++i) {
        float inv = __fdividef(1.f, sums[i]);
        out[(size_t)(b * SS + i0 + i) * SS + j] = e[i] * inv;
    }
}

// ---------------------------------------------------------------------------
extern "C" void kernel_launch(void* const* d_in, const int* in_sizes, int n_in,
                              void* d_out, int out_size)
{
    const float* x    = (const float*)d_in[0];  // relation_hidden (B,S,H)
    const float* wta  = (const float*)d_in[1];  // (A,H)
    const float* wja  = (const float*)d_in[2];  // (A,H)
    const float* bias = (const float*)d_in[3];  // (1,1,1,A)
    const float* v    = (const float*)d_in[4];  // (1,A)

    proj_gemm_kernel<<<ROWS / 32, 256>>>(x, wta, wja, bias);
    attn_kernel<<<ROWS / TI, 512>>>(v, (float*)d_out);
}

// round 8
// speedup vs baseline: 1.0435x; 1.0435x over previous
#include <cuda_runtime.h>
#include <cuda_fp16.h>
#include <math.h>

#define BB 8
#define SS 512
#define HH 256
#define AA 64
#define ROWS (BB*SS)   // 4096
#define TI 8           // i-rows per attn block

// Scratch (allocation-free rule: __device__ globals)
__device__ float        g_ta[ROWS * AA];         // [row][a], bias folded in (f32)
__device__ unsigned int g_jaT16[(AA/2) * ROWS];  // [a-pair][row], half2 (ja_2p, ja_2p+1)

namespace rk {

// packed f32x2 helpers (Blackwell FFMA2 — only reachable via PTX fma.rn.f32x2)
union F2 { unsigned long long u; float2 f; };

__device__ __forceinline__ unsigned long long fma2(
    unsigned long long a, unsigned long long b, unsigned long long c) {
    unsigned long long d;
    asm("fma.rn.f32x2 %0, %1, %2, %3;" : "=l"(d) : "l"(a), "l"(b), "l"(c));
    return d;
}

// fast packed tanh (MUFU.TANH f16x2)
__device__ __forceinline__ __half2 rk_tanh_f16x2(__half2 x) {
    unsigned int xi = *reinterpret_cast<unsigned int*>(&x);
    unsigned int yi;
    asm("tanh.approx.f16x2 %0, %1;" : "=r"(yi) : "r"(xi));
    return *reinterpret_cast<__half2*>(&yi);
}

// mixed-precision FMA: f16 x f16 + f32 -> f32 (sm_100 HFMA.F32; no XU, no F2F)
__device__ __forceinline__ float fmah(unsigned short a, unsigned short b, float c) {
    float d;
    asm("fma.rn.f32.f16 %0, %1, %2, %3;" : "=f"(d) : "h"(a), "h"(b), "f"(c));
    return d;
}

} // namespace rk

using rk::F2;
using rk::fma2;
using rk::rk_tanh_f16x2;
using rk::fmah;

// ---------------------------------------------------------------------------
// Kernel 1: tiled GEMM with packed f32x2 FMA. 128 blocks x 256 threads.
// Block: 32 rows x 128 cols. W read directly from w_ta/w_ja; conflict-free
// STS scatter. Epilogue: ta -> f32 [row][a] (+bias); ja -> f16x2 [a-pair][row].
// ---------------------------------------------------------------------------
#define KC 64
__global__ void __launch_bounds__(256) proj_gemm_kernel(
    const float* __restrict__ x,
    const float* __restrict__ w_ta,
    const float* __restrict__ w_ja,
    const float* __restrict__ bias)
{
    __shared__ float Xs[32][KC];        // [r][kk]  8KB
    __shared__ float Ws[KC][128];       // [kk][a2] 32KB

    const int tid = threadIdx.x;
    const int rt  = tid >> 5;           // 0..7  (row tile)
    const int ct  = tid & 31;           // 0..31 (col tile)
    const int row0 = blockIdx.x * 32;

    const int a2w = tid & 127;
    const int hiw = tid >> 7;
    const float* wsrc = (a2w < 64) ? (w_ta + (size_t)a2w * HH)
                                   : (w_ja + (size_t)(a2w - 64) * HH);

    F2 acc[4][2];
#pragma unroll
    for (int i = 0; i < 4; ++i) { acc[i][0].u = 0ull; acc[i][1].u = 0ull; }

    for (int kc = 0; kc < HH; kc += KC) {
#pragma unroll
        for (int l = tid; l < 512; l += 256) {
            int r = l >> 4;
            int q = l & 15;
            float4 xv = *reinterpret_cast<const float4*>(
                x + (size_t)(row0 + r) * HH + kc + q * 4);
            *reinterpret_cast<float4*>(&Xs[r][q * 4]) = xv;
        }
#pragma unroll
        for (int m = 0; m < 8; ++m) {
            int kk4 = 2 * m + hiw;
            float4 f = *reinterpret_cast<const float4*>(wsrc + kc + kk4 * 4);
            Ws[kk4 * 4 + 0][a2w] = f.x;
            Ws[kk4 * 4 + 1][a2w] = f.y;
            Ws[kk4 * 4 + 2][a2w] = f.z;
            Ws[kk4 * 4 + 3][a2w] = f.w;
        }
        __syncthreads();

#pragma unroll
        for (int kk = 0; kk < KC; ++kk) {
            ulonglong2 wv = *reinterpret_cast<ulonglong2*>(&Ws[kk][ct * 4]);
            F2 x0, x1, x2, x3;
            float a0 = Xs[rt * 4 + 0][kk];
            float a1 = Xs[rt * 4 + 1][kk];
            float a2v = Xs[rt * 4 + 2][kk];
            float a3 = Xs[rt * 4 + 3][kk];
            x0.f = make_float2(a0, a0);
            x1.f = make_float2(a1, a1);
            x2.f = make_float2(a2v, a2v);
            x3.f = make_float2(a3, a3);
            acc[0][0].u = fma2(x0.u, wv.x, acc[0][0].u);
            acc[0][1].u = fma2(x0.u, wv.y, acc[0][1].u);
            acc[1][0].u = fma2(x1.u, wv.x, acc[1][0].u);
            acc[1][1].u = fma2(x1.u, wv.y, acc[1][1].u);
            acc[2][0].u = fma2(x2.u, wv.x, acc[2][0].u);
            acc[2][1].u = fma2(x2.u, wv.y, acc[2][1].u);
            acc[3][0].u = fma2(x3.u, wv.x, acc[3][0].u);
            acc[3][1].u = fma2(x3.u, wv.y, acc[3][1].u);
        }
        __syncthreads();
    }

    const int c0 = ct * 4;
    if (c0 < 64) {
        float4 bb = *reinterpret_cast<const float4*>(bias + c0);
#pragma unroll
        for (int i = 0; i < 4; ++i) {
            int row = row0 + rt * 4 + i;
            float4 o;
            o.x = acc[i][0].f.x + bb.x;
            o.y = acc[i][0].f.y + bb.y;
            o.z = acc[i][1].f.x + bb.z;
            o.w = acc[i][1].f.y + bb.w;
            *reinterpret_cast<float4*>(&g_ta[(size_t)row * AA + c0]) = o;
        }
    } else {
        const int ab  = c0 - 64;
        const int ap0 = ab >> 1;
        uint4 s0, s1;
        {
            __half2 h;
            h = __floats2half2_rn(acc[0][0].f.x, acc[0][0].f.y); s0.x = *reinterpret_cast<unsigned int*>(&h);
            h = __floats2half2_rn(acc[1][0].f.x, acc[1][0].f.y); s0.y = *reinterpret_cast<unsigned int*>(&h);
            h = __floats2half2_rn(acc[2][0].f.x, acc[2][0].f.y); s0.z = *reinterpret_cast<unsigned int*>(&h);
            h = __floats2half2_rn(acc[3][0].f.x, acc[3][0].f.y); s0.w = *reinterpret_cast<unsigned int*>(&h);
            h = __floats2half2_rn(acc[0][1].f.x, acc[0][1].f.y); s1.x = *reinterpret_cast<unsigned int*>(&h);
            h = __floats2half2_rn(acc[1][1].f.x, acc[1][1].f.y); s1.y = *reinterpret_cast<unsigned int*>(&h);
            h = __floats2half2_rn(acc[2][1].f.x, acc[2][1].f.y); s1.z = *reinterpret_cast<unsigned int*>(&h);
            h = __floats2half2_rn(acc[3][1].f.x, acc[3][1].f.y); s1.w = *reinterpret_cast<unsigned int*>(&h);
        }
        const int rowb = row0 + rt * 4;
        *reinterpret_cast<uint4*>(&g_jaT16[(size_t)ap0 * ROWS + rowb])       = s0;
        *reinterpret_cast<uint4*>(&g_jaT16[(size_t)(ap0 + 1) * ROWS + rowb]) = s1;
    }
}

// ---------------------------------------------------------------------------
// Kernel 2: scores + softmax. f16x2 tanh + mixed fma.rn.f32.f16 accumulation:
// zero F2F in the loop, f32 accumulators, no serial chains.
// 512 blocks x 512 threads; thread = one j; i-pairs ride f16x2 lanes.
// ---------------------------------------------------------------------------
__global__ void __launch_bounds__(512) attn_kernel(
    const float* __restrict__ v,
    float* __restrict__ out)
{
    __shared__ __half2 ta16[AA][4];     // [a][i-pair p], 16B rows -> LDS.128
    __shared__ unsigned int v16p[AA/2]; // packed (v_2p, v_2p+1) halves
    __shared__ float redm[TI][16];
    __shared__ float reds[TI][16];
    __shared__ float gmaxs[TI];
    __shared__ float sums[TI];

    const int blk = blockIdx.x;           // 0..511
    const int b   = blk >> 6;             // batch
    const int i0  = (blk & 63) * TI;      // first i-row
    const int j   = threadIdx.x;          // 0..511
    const int lane = j & 31;
    const int warp = j >> 5;              // 0..15

    // setup: pack ta into f16x2 i-pairs; pack v as half pairs
    if (j < 256) {
        int a = j >> 2, p = j & 3;
        float lo = g_ta[(size_t)(b * SS + i0 + 2 * p)     * AA + a];
        float hi = g_ta[(size_t)(b * SS + i0 + 2 * p + 1) * AA + a];
        ta16[a][p] = __floats2half2_rn(lo, hi);
    } else if (j < 256 + AA / 2) {
        int ap = j - 256;
        __half2 h = __floats2half2_rn(v[2 * ap], v[2 * ap + 1]);
        v16p[ap] = *reinterpret_cast<unsigned int*>(&h);
    }
    __syncthreads();

    float acc[TI];
#pragma unroll
    for (int i = 0; i < TI; ++i) acc[i] = 0.f;

    const unsigned int* jp = g_jaT16 + b * SS + j;
#pragma unroll 4
    for (int ap = 0; ap < AA / 2; ++ap) {
        unsigned int jraw = jp[(size_t)ap * ROWS];
        __half2 jv  = *reinterpret_cast<__half2*>(&jraw);   // (ja_{2ap}, ja_{2ap+1})
        __half2 jv0 = __low2half2(jv);                      // operand .H0_H0
        __half2 jv1 = __high2half2(jv);                     // operand .H1_H1
        unsigned int vp = v16p[ap];
        unsigned short vh0 = (unsigned short)(vp & 0xffffu);
        unsigned short vh1 = (unsigned short)(vp >> 16);
        uint4 ra0 = *reinterpret_cast<const uint4*>(&ta16[2 * ap][0]);
        uint4 ra1 = *reinterpret_cast<const uint4*>(&ta16[2 * ap + 1][0]);
        const unsigned int* pa0 = reinterpret_cast<const unsigned int*>(&ra0);
        const unsigned int* pa1 = reinterpret_cast<const unsigned int*>(&ra1);
#pragma unroll
        for (int p = 0; p < 4; ++p) {
            __half2 t0 = rk_tanh_f16x2(__hadd2(*reinterpret_cast<const __half2*>(&pa0[p]), jv0));
            __half2 t1 = rk_tanh_f16x2(__hadd2(*reinterpret_cast<const __half2*>(&pa1[p]), jv1));
            unsigned int u0 = *reinterpret_cast<unsigned int*>(&t0);
            unsigned int u1 = *reinterpret_cast<unsigned int*>(&t1);
            // mixed-precision FMAs into f32 accumulators (fma pipe, no XU)
            acc[2 * p]     = fmah((unsigned short)(u0 & 0xffffu), vh0, acc[2 * p]);
            acc[2 * p]     = fmah((unsigned short)(u1 & 0xffffu), vh1, acc[2 * p]);
            acc[2 * p + 1] = fmah((unsigned short)(u0 >> 16),     vh0, acc[2 * p + 1]);
            acc[2 * p + 1] = fmah((unsigned short)(u1 >> 16),     vh1, acc[2 * p + 1]);
        }
    }

    // ---- block max per row ----
#pragma unroll
    for (int i = 0; i < TI; ++i) {
        float mx = acc[i];
#pragma unroll
        for (int o = 16; o; o >>= 1) mx = fmaxf(mx, __shfl_xor_sync(0xffffffffu, mx, o));
        if (lane == 0) redm[i][warp] = mx;
    }
    __syncthreads();
    if (warp < TI) {
        float m = (lane < 16) ? redm[warp][lane] : -INFINITY;
#pragma unroll
        for (int o = 8; o; o >>= 1) m = fmaxf(m, __shfl_xor_sync(0xffffffffu, m, o));
        if (lane == 0) gmaxs[warp] = m;
    }
    __syncthreads();

    // ---- exp + block sum per row ----
    float e[TI];
#pragma unroll
    for (int i = 0; i < TI; ++i) {
        e[i] = __expf(acc[i] - gmaxs[i]);
        float sm = e[i];
#pragma unroll
        for (int o = 16; o; o >>= 1) sm += __shfl_xor_sync(0xffffffffu, sm, o);
        if (lane == 0) reds[i][warp] = sm;
    }
    __syncthreads();
    if (warp < TI) {
        float t = (lane < 16) ? reds[warp][lane] : 0.f;
#pragma unroll
        for (int o = 8; o; o >>= 1) t += __shfl_xor_sync(0xffffffffu, t, o);
        if (lane == 0) sums[warp] = t;
    }
    __syncthreads();

#pragma unroll
    for (int i = 0; i < TI; ++i) {
        float inv = __fdividef(1.f, sums[i]);
        out[(size_t)(b * SS + i0 + i) * SS + j] = e[i] * inv;
    }
}

// ---------------------------------------------------------------------------
extern "C" void kernel_launch(void* const* d_in, const int* in_sizes, int n_in,
                              void* d_out, int out_size)
{
    const float* x    = (const float*)d_in[0];  // relation_hidden (B,S,H)
    const float* wta  = (const float*)d_in[1];  // (A,H)
    const float* wja  = (const float*)d_in[2];  // (A,H)
    const float* bias = (const float*)d_in[3];  // (1,1,1,A)
    const float* v    = (const float*)d_in[4];  // (1,A)

    proj_gemm_kernel<<<ROWS / 32, 256>>>(x, wta, wja, bias);
    attn_kernel<<<ROWS / TI, 512>>>(v, (float*)d_out);
}